// round 4
// baseline (speedup 1.0000x reference)
#include <cuda_runtime.h>
#include <cuda_fp16.h>
#include <cstdint>

#define NN 100000
#define NE 1600000
#define FH 128
#define NG 256
#define NA 32

#define SCAN_BS 512
#define SCAN_NB ((NN + SCAN_BS - 1) / SCAN_BS)   // 196
#define DEGB 148                                  // deg-histogram blocks in fused kernel

// ---------------- scratch (device globals; no runtime allocation) ----------
__device__ __half    g_hh[(size_t)NN * FH];   // GEMM output (fp16, 25.6MB)
__device__ __half    g_th[(size_t)NN * FH];   // layer-1 output t (fp16, 25.6MB)
__device__ int       g_deg[NN];
__device__ float     g_dinv[NN];
__device__ int       g_off[NN + 1];
__device__ int       g_cur[NN];
__device__ int       g_esrc[NE];
__device__ int       g_bsum[SCAN_NB];
__device__ float     g_pool[NG * FH];
__device__ int       g_cnt[NG];
// W pre-packed into per-lane mma B-fragment layout:
// [wsel][pass(hi/lo) 2][kstep 8][ntile 16][lane 32][reg 2]  (uint32 = half2)
__device__ uint32_t  g_wpack[2][16384];

// ---------------- helpers ---------------------------------------------------
__device__ __forceinline__ uint32_t smem_u32(const void* p) {
    uint32_t a;
    asm("{ .reg .u64 t; cvta.to.shared.u64 t, %1; cvt.u32.u64 %0, t; }"
        : "=r"(a) : "l"(p));
    return a;
}
__device__ __forceinline__ uint32_t h2u(float a, float b) {
    __half2 h = __floats2half2_rn(a, b);
    return *(uint32_t*)&h;
}
__device__ __forceinline__ void mma16816(float* c, const uint32_t* a,
                                         uint32_t b0, uint32_t b1) {
    asm volatile(
        "mma.sync.aligned.m16n8k16.row.col.f32.f16.f16.f32 "
        "{%0,%1,%2,%3}, {%4,%5,%6,%7}, {%8,%9}, {%0,%1,%2,%3};"
        : "+f"(c[0]), "+f"(c[1]), "+f"(c[2]), "+f"(c[3])
        : "r"(a[0]), "r"(a[1]), "r"(a[2]), "r"(a[3]), "r"(b0), "r"(b1));
}

// ---------------- weight prep: fp32 W[k][n] -> packed hi/lo B fragments -----
__global__ void k_prepw(const float* __restrict__ W1, const float* __restrict__ W2) {
    int gid = blockIdx.x * blockDim.x + threadIdx.x;   // < 32768
    if (gid >= 32768) return;
    int wsel = gid >> 14;
    int rem  = gid & 16383;
    int pass = rem >> 13;
    int r2   = rem & 8191;
    int reg  = r2 & 1;
    int lane = (r2 >> 1) & 31;
    int nt   = (r2 >> 6) & 15;
    int ks   = (r2 >> 10) & 7;
    const float* W = wsel ? W2 : W1;
    int k = ks * 16 + (lane & 3) * 2 + reg * 8;
    int n = nt * 8 + (lane >> 2);
    float v0 = W[k * FH + n];
    float v1 = W[(k + 1) * FH + n];
    __half h0, h1;
    if (pass == 0) {
        h0 = __float2half_rn(v0);
        h1 = __float2half_rn(v1);
    } else {
        h0 = __float2half_rn(v0 - __half2float(__float2half_rn(v0)));
        h1 = __float2half_rn(v1 - __half2float(__float2half_rn(v1)));
    }
    __half2 p = __halves2half2(h0, h1);
    g_wpack[wsel][rem] = *(uint32_t*)&p;
}

// ---------------- small utility kernels ------------------------------------
__global__ void k_zero1() {
    int i = blockIdx.x * blockDim.x + threadIdx.x;
    if (i < NN) g_deg[i] = 0;
}
__global__ void k_zero2() {
    int i = blockIdx.x * blockDim.x + threadIdx.x;
    if (i < NG * FH) g_pool[i] = 0.f;
    if (i < NG) g_cnt[i] = 0;
}

__global__ void k_scan1() {
    __shared__ int s[SCAN_BS];
    int idx = blockIdx.x * SCAN_BS + threadIdx.x;
    int v = (idx < NN) ? g_deg[idx] : 0;
    if (idx < NN) g_dinv[idx] = rsqrtf((float)v + 1.0f);
    s[threadIdx.x] = v;
    __syncthreads();
    for (int d = 1; d < SCAN_BS; d <<= 1) {
        int t = (threadIdx.x >= d) ? s[threadIdx.x - d] : 0;
        __syncthreads();
        s[threadIdx.x] += t;
        __syncthreads();
    }
    if (idx < NN) g_off[idx + 1] = s[threadIdx.x];
    if (threadIdx.x == SCAN_BS - 1) g_bsum[blockIdx.x] = s[SCAN_BS - 1];
}

__global__ void k_scan2() {
    __shared__ int s[256];
    int v = (threadIdx.x < SCAN_NB) ? g_bsum[threadIdx.x] : 0;
    s[threadIdx.x] = v;
    __syncthreads();
    for (int d = 1; d < 256; d <<= 1) {
        int t = (threadIdx.x >= d) ? s[threadIdx.x - d] : 0;
        __syncthreads();
        s[threadIdx.x] += t;
        __syncthreads();
    }
    if (threadIdx.x < SCAN_NB) g_bsum[threadIdx.x] = s[threadIdx.x];
}

__global__ void k_scan3() {
    int idx = blockIdx.x * SCAN_BS + threadIdx.x;
    int base = (blockIdx.x == 0) ? 0 : g_bsum[blockIdx.x - 1];
    if (idx < NN) {
        int v = g_off[idx + 1] + base;
        g_off[idx + 1] = v;
        if (idx + 1 < NN) g_cur[idx + 1] = v;
    }
    if (idx == 0) { g_off[0] = 0; g_cur[0] = 0; }
}

__global__ void k_fill(const int* __restrict__ ei) {
    int e = blockIdx.x * blockDim.x + threadIdx.x;
    if (e < NE) {
        int src = ei[e];
        int dst = ei[NE + e];
        int p = atomicAdd(&g_cur[dst], 1);
        g_esrc[p] = src;
    }
}

// ---------------- fused GEMM (+optional degree histogram) -------------------
// Blocks [0, degb): grid-stride degree histogram over edges (L2-atomic bound).
// Blocks [degb, ...): 128x128x128 mma.sync GEMM tile, Y = scale .* (X@(Wh+Wl)).
// smem: Xs 32KB (swizzled fp16) + W pack 64KB = 96KB.
#define GEMM_SMEM (32768 + 65536)
__global__ void __launch_bounds__(256, 2)
k_gd(const float* __restrict__ Xf, const __half* __restrict__ Xh,
     int wsel, __half* __restrict__ Y, int nrows,
     const int* __restrict__ ei, int degb, const float* __restrict__ dinvp) {
    int tid = threadIdx.x;
    if ((int)blockIdx.x < degb) {
        int stride = degb * 256;
        for (int e = blockIdx.x * 256 + tid; e < NE; e += stride)
            atomicAdd(&g_deg[__ldg(&ei[NE + e])], 1);
        return;
    }
    extern __shared__ char sm[];
    char* Xs = sm;                               // [128 rows][16 chunks of 16B], swizzled
    uint32_t* Wsm = (uint32_t*)(sm + 32768);     // 16384 u32
    int wid = tid >> 5, lane = tid & 31;
    int row0 = (blockIdx.x - degb) * 128;

    // copy packed W (both passes, 64KB)
    {
        const uint4* src = (const uint4*)g_wpack[wsel];
        uint4* dst = (uint4*)Wsm;
#pragma unroll
        for (int i = 0; i < 16; i++) dst[tid + 256 * i] = src[tid + 256 * i];
    }
    // fill Xs: row r, chunk c (8 fp16 = 16B); phys chunk = c ^ (r&7)
    if (Xf) {
        const float4* X4 = (const float4*)Xf;
#pragma unroll
        for (int it = 0; it < 8; it++) {
            int g = tid + 256 * it;
            int r = g >> 4, c = g & 15;
            uint4 o = make_uint4(0, 0, 0, 0);
            if (row0 + r < nrows) {
                float4 a = X4[(size_t)(row0 + r) * 32 + c * 2];
                float4 b = X4[(size_t)(row0 + r) * 32 + c * 2 + 1];
                o.x = h2u(a.x, a.y); o.y = h2u(a.z, a.w);
                o.z = h2u(b.x, b.y); o.w = h2u(b.z, b.w);
            }
            *(uint4*)(Xs + r * 256 + ((c ^ (r & 7)) * 16)) = o;
        }
    } else {
        const uint4* X4 = (const uint4*)Xh;
#pragma unroll
        for (int it = 0; it < 8; it++) {
            int g = tid + 256 * it;
            int r = g >> 4, c = g & 15;
            uint4 o = make_uint4(0, 0, 0, 0);
            if (row0 + r < nrows) o = X4[(size_t)(row0 + r) * 16 + c];
            *(uint4*)(Xs + r * 256 + ((c ^ (r & 7)) * 16)) = o;
        }
    }
    __syncthreads();

    int wr = wid & 3;        // row group: rows 32*wr .. 32*wr+31
    int wc = wid >> 2;       // col group: cols 64*wc .. 64*wc+63
    float acc[2][8][4];
#pragma unroll
    for (int mt = 0; mt < 2; mt++)
#pragma unroll
        for (int nt = 0; nt < 8; nt++)
#pragma unroll
            for (int q = 0; q < 4; q++) acc[mt][nt][q] = 0.f;

    uint32_t smx = smem_u32(Xs);
    const uint2* W2v = (const uint2*)Wsm;   // [pass*4096 + (ks*16+ntg)*32 + lane]

#pragma unroll
    for (int ks = 0; ks < 8; ks++) {
        uint32_t a[2][4];
#pragma unroll
        for (int mt = 0; mt < 2; mt++) {
            int sub = lane >> 3;                       // 0..3
            int r = 32 * wr + 16 * mt + (lane & 7) + (sub & 1) * 8;
            int c = ks * 2 + (sub >> 1);
            uint32_t addr = smx + r * 256 + ((c ^ (r & 7)) * 16);
            asm volatile(
                "ldmatrix.sync.aligned.m8n8.x4.shared.b16 {%0,%1,%2,%3}, [%4];"
                : "=r"(a[mt][0]), "=r"(a[mt][1]), "=r"(a[mt][2]), "=r"(a[mt][3])
                : "r"(addr));
        }
#pragma unroll
        for (int nt = 0; nt < 8; nt++) {
            int ntg = 8 * wc + nt;
            uint2 bh = W2v[(ks * 16 + ntg) * 32 + lane];
            uint2 bl = W2v[4096 + (ks * 16 + ntg) * 32 + lane];
            mma16816(acc[0][nt], a[0], bh.x, bh.y);
            mma16816(acc[1][nt], a[1], bh.x, bh.y);
            mma16816(acc[0][nt], a[0], bl.x, bl.y);
            mma16816(acc[1][nt], a[1], bl.x, bl.y);
        }
    }

    // epilogue: optional dinv scale, store fp16
#pragma unroll
    for (int mt = 0; mt < 2; mt++) {
        int r0 = row0 + 32 * wr + 16 * mt + (lane >> 2);
        int r1 = r0 + 8;
        float s0 = 1.f, s1 = 1.f;
        if (dinvp) {
            s0 = (r0 < nrows) ? dinvp[r0] : 0.f;
            s1 = (r1 < nrows) ? dinvp[r1] : 0.f;
        }
#pragma unroll
        for (int nt = 0; nt < 8; nt++) {
            int col = 64 * wc + 8 * nt + (lane & 3) * 2;
            if (r0 < nrows)
                *(uint32_t*)&Y[(size_t)r0 * FH + col] =
                    h2u(acc[mt][nt][0] * s0, acc[mt][nt][1] * s0);
            if (r1 < nrows)
                *(uint32_t*)&Y[(size_t)r1 * FH + col] =
                    h2u(acc[mt][nt][2] * s1, acc[mt][nt][3] * s1);
        }
    }
}

// ---------------- aggregation: one warp per dst node, fp16 gather -----------
// prescaled=1: H holds dinv.*h; out = relu(dinv_d*(sum h'[src] + h'[d]) + b)
// prescaled=0: H holds h;       out = relu(dinv_d*(sum dinv[s]*h[s] + dinv_d*h[d]) + b)
__global__ void k_agg(const __half* __restrict__ H, const float* __restrict__ bias,
                      const int* __restrict__ batch, __half* __restrict__ OutH,
                      int do_pool, int prescaled) {
    int node = (blockIdx.x * blockDim.x + threadIdx.x) >> 5;
    int lane = threadIdx.x & 31;
    if (node >= NN) return;
    int s = g_off[node];
    int e = g_off[node + 1];
    const uint2* H2 = (const uint2*)H;    // 4 halves per lane, 32 lanes = 128
    float a0 = 0.f, a1 = 0.f, a2 = 0.f, a3 = 0.f;
    float di = g_dinv[node];
    if (prescaled) {
#pragma unroll 4
        for (int j = s; j < e; j++) {
            int src = __ldg(&g_esrc[j]);
            uint2 v = __ldg(&H2[(size_t)src * 32 + lane]);
            float2 f0 = __half22float2(*(__half2*)&v.x);
            float2 f1 = __half22float2(*(__half2*)&v.y);
            a0 += f0.x; a1 += f0.y; a2 += f1.x; a3 += f1.y;
        }
        uint2 v = __ldg(&H2[(size_t)node * 32 + lane]);   // self (already dinv*h)
        float2 f0 = __half22float2(*(__half2*)&v.x);
        float2 f1 = __half22float2(*(__half2*)&v.y);
        a0 += f0.x; a1 += f0.y; a2 += f1.x; a3 += f1.y;
    } else {
#pragma unroll 4
        for (int j = s; j < e; j++) {
            int src = __ldg(&g_esrc[j]);
            float c = __ldg(&g_dinv[src]);
            uint2 v = __ldg(&H2[(size_t)src * 32 + lane]);
            float2 f0 = __half22float2(*(__half2*)&v.x);
            float2 f1 = __half22float2(*(__half2*)&v.y);
            a0 += c * f0.x; a1 += c * f0.y; a2 += c * f1.x; a3 += c * f1.y;
        }
        uint2 v = __ldg(&H2[(size_t)node * 32 + lane]);   // self: + dinv_d*h_d
        float2 f0 = __half22float2(*(__half2*)&v.x);
        float2 f1 = __half22float2(*(__half2*)&v.y);
        a0 += di * f0.x; a1 += di * f0.y; a2 += di * f1.x; a3 += di * f1.y;
    }
    float4 bv = __ldg(&((const float4*)bias)[lane]);
    float r0 = fmaxf(di * a0 + bv.x, 0.f);
    float r1 = fmaxf(di * a1 + bv.y, 0.f);
    float r2 = fmaxf(di * a2 + bv.z, 0.f);
    float r3 = fmaxf(di * a3 + bv.w, 0.f);
    if (OutH) {
        uint2 o;
        o.x = h2u(r0, r1);
        o.y = h2u(r2, r3);
        ((uint2*)OutH)[(size_t)node * 32 + lane] = o;
    }
    if (do_pool) {
        int b = __ldg(&batch[node]);
        float* p = &g_pool[b * FH + lane * 4];
        atomicAdd(p + 0, r0);
        atomicAdd(p + 1, r1);
        atomicAdd(p + 2, r2);
        atomicAdd(p + 3, r3);
        if (lane == 0) atomicAdd(&g_cnt[b], 1);
    }
}

// ---------------- final MLP head: one block per graph -----------------------
__global__ void k_mlp(const float* __restrict__ Wl1, const float* __restrict__ bl1,
                      const float* __restrict__ Wl2, const float* __restrict__ bl2,
                      float* __restrict__ out) {
    __shared__ float gv[FH];
    __shared__ float tv[FH];
    int b = blockIdx.x, tid = threadIdx.x;
    float c = fmaxf((float)g_cnt[b], 1.0f);
    gv[tid] = g_pool[b * FH + tid] / c;
    __syncthreads();
    float s = bl1[tid];
#pragma unroll 8
    for (int k = 0; k < FH; k++) s += gv[k] * Wl1[k * FH + tid];
    tv[tid] = fmaxf(s, 0.f);
    __syncthreads();
    if (tid < NA) {
        float o = bl2[tid];
#pragma unroll 8
        for (int k = 0; k < FH; k++) o += tv[k] * Wl2[k * NA + tid];
        out[b * NA + tid] = o;
    }
}

// ---------------- launch ----------------------------------------------------
extern "C" void kernel_launch(void* const* d_in, const int* in_sizes, int n_in,
                              void* d_out, int out_size) {
    const float* x   = (const float*)d_in[0];
    const int*   ei  = (const int*)d_in[1];
    const int*   bat = (const int*)d_in[2];
    const float* W1  = (const float*)d_in[3];
    const float* b1  = (const float*)d_in[4];
    const float* W2  = (const float*)d_in[5];
    const float* b2  = (const float*)d_in[6];
    const float* Wl1 = (const float*)d_in[7];
    const float* bl1 = (const float*)d_in[8];
    const float* Wl2 = (const float*)d_in[9];
    const float* bl2 = (const float*)d_in[10];
    float* out = (float*)d_out;

    __half *phh = nullptr, *pth = nullptr;
    float* pdinv = nullptr;
    cudaGetSymbolAddress((void**)&phh, g_hh);
    cudaGetSymbolAddress((void**)&pth, g_th);
    cudaGetSymbolAddress((void**)&pdinv, g_dinv);

    cudaFuncSetAttribute(k_gd, cudaFuncAttributeMaxDynamicSharedMemorySize,
                         GEMM_SMEM);

    const int GB = (NN + 127) / 128;   // 782

    k_prepw<<<128, 256>>>(W1, W2);                                    // 1
    k_zero1<<<(NN + 255) / 256, 256>>>();                             // 2
    k_zero2<<<(NG * FH + 255) / 256, 256>>>();                        // 3
    // 4: fused layer-1 GEMM (unscaled) + degree histogram  [profiled]
    k_gd<<<GB + DEGB, 256, GEMM_SMEM>>>(x, nullptr, 0, phh, NN, ei, DEGB, nullptr);
    k_scan1<<<SCAN_NB, SCAN_BS>>>();                                  // 5 (+dinv)
    k_scan2<<<1, 256>>>();                                            // 6
    k_scan3<<<SCAN_NB, SCAN_BS>>>();                                  // 7 (+cur)
    k_fill<<<(NE + 255) / 256, 256>>>(ei);                            // 8
    k_agg<<<(NN * 32 + 255) / 256, 256>>>(phh, b1, bat, pth, 0, 0);   // 9
    k_gd<<<GB, 256, GEMM_SMEM>>>(nullptr, pth, 1, phh, NN, ei, 0, pdinv); // 10
    k_agg<<<(NN * 32 + 255) / 256, 256>>>(phh, b2, bat, nullptr, 1, 1);   // 11
    k_mlp<<<NG, FH>>>(Wl1, bl1, Wl2, bl2, out);                       // 12
}

// round 5
// speedup vs baseline: 1.6102x; 1.6102x over previous
#include <cuda_runtime.h>
#include <cuda_fp16.h>
#include <cstdint>

#define NN 100000
#define NE 1600000
#define FH 128
#define NG 256
#define NA 32

#define SCAN_BS 512
#define SCAN_NB ((NN + SCAN_BS - 1) / SCAN_BS)   // 196

// ---------------- scratch (device globals; no runtime allocation) ----------
__device__ __half    g_hh[(size_t)NN * FH];   // dinv-prescaled GEMM output (25.6MB)
__device__ __half    g_th[(size_t)NN * FH];   // layer-1 output t (25.6MB)
__device__ int       g_deg[NN];
__device__ float     g_dinv[NN];
__device__ int       g_off[NN + 1];
__device__ int       g_cur[NN];
__device__ int       g_esrc[NE];
__device__ int       g_bsum[SCAN_NB];
__device__ float     g_pool[NG * FH];
__device__ int       g_cnt[NG];
// W pre-packed into per-lane mma B-fragment layout:
// [wsel][pass(hi/lo) 2][kstep 8][ntile 16][lane 32][reg 2]  (uint32 = half2)
__device__ uint32_t  g_wpack[2][16384];

// ---------------- helpers ---------------------------------------------------
__device__ __forceinline__ uint32_t smem_u32(const void* p) {
    uint32_t a;
    asm("{ .reg .u64 t; cvta.to.shared.u64 t, %1; cvt.u32.u64 %0, t; }"
        : "=r"(a) : "l"(p));
    return a;
}
__device__ __forceinline__ uint32_t h2u(float a, float b) {
    __half2 h = __floats2half2_rn(a, b);
    return *(uint32_t*)&h;
}
__device__ __forceinline__ void mma16816(float* c, const uint32_t* a,
                                         uint32_t b0, uint32_t b1) {
    asm volatile(
        "mma.sync.aligned.m16n8k16.row.col.f32.f16.f16.f32 "
        "{%0,%1,%2,%3}, {%4,%5,%6,%7}, {%8,%9}, {%0,%1,%2,%3};"
        : "+f"(c[0]), "+f"(c[1]), "+f"(c[2]), "+f"(c[3])
        : "r"(a[0]), "r"(a[1]), "r"(a[2]), "r"(a[3]), "r"(b0), "r"(b1));
}

// -------- weight prep (blocks <128) fused with scratch zeroing (rest) -------
__global__ void k_prepw(const float* __restrict__ W1, const float* __restrict__ W2) {
    if (blockIdx.x >= 128) {
        int i = (blockIdx.x - 128) * 256 + threadIdx.x;
        if (i < NN) g_deg[i] = 0;
        if (i < NG * FH) g_pool[i] = 0.f;
        if (i < NG) g_cnt[i] = 0;
        return;
    }
    int gid = blockIdx.x * 256 + threadIdx.x;   // < 32768
    int wsel = gid >> 14;
    int rem  = gid & 16383;
    int pass = rem >> 13;
    int r2   = rem & 8191;
    int reg  = r2 & 1;
    int lane = (r2 >> 1) & 31;
    int nt   = (r2 >> 6) & 15;
    int ks   = (r2 >> 10) & 7;
    const float* W = wsel ? W2 : W1;
    int k = ks * 16 + (lane & 3) * 2 + reg * 8;
    int n = nt * 8 + (lane >> 2);
    float v0 = W[k * FH + n];
    float v1 = W[(k + 1) * FH + n];
    __half h0, h1;
    if (pass == 0) {
        h0 = __float2half_rn(v0);
        h1 = __float2half_rn(v1);
    } else {
        h0 = __float2half_rn(v0 - __half2float(__float2half_rn(v0)));
        h1 = __float2half_rn(v1 - __half2float(__float2half_rn(v1)));
    }
    __half2 p = __halves2half2(h0, h1);
    g_wpack[wsel][rem] = *(uint32_t*)&p;
}

// ---------------- CSR build ---------------------------------------------------
__global__ void k_deg(const int* __restrict__ ei) {
    int e = blockIdx.x * blockDim.x + threadIdx.x;
    if (e < NE) atomicAdd(&g_deg[ei[NE + e]], 1);
}

__global__ void k_scan1() {
    __shared__ int s[SCAN_BS];
    int idx = blockIdx.x * SCAN_BS + threadIdx.x;
    int v = (idx < NN) ? g_deg[idx] : 0;
    if (idx < NN) g_dinv[idx] = rsqrtf((float)v + 1.0f);
    s[threadIdx.x] = v;
    __syncthreads();
    for (int d = 1; d < SCAN_BS; d <<= 1) {
        int t = (threadIdx.x >= d) ? s[threadIdx.x - d] : 0;
        __syncthreads();
        s[threadIdx.x] += t;
        __syncthreads();
    }
    if (idx < NN) g_off[idx + 1] = s[threadIdx.x];
    if (threadIdx.x == SCAN_BS - 1) g_bsum[blockIdx.x] = s[SCAN_BS - 1];
}

__global__ void k_scan2() {
    __shared__ int s[256];
    int v = (threadIdx.x < SCAN_NB) ? g_bsum[threadIdx.x] : 0;
    s[threadIdx.x] = v;
    __syncthreads();
    for (int d = 1; d < 256; d <<= 1) {
        int t = (threadIdx.x >= d) ? s[threadIdx.x - d] : 0;
        __syncthreads();
        s[threadIdx.x] += t;
        __syncthreads();
    }
    if (threadIdx.x < SCAN_NB) g_bsum[threadIdx.x] = s[threadIdx.x];
}

__global__ void k_scan3() {
    int idx = blockIdx.x * SCAN_BS + threadIdx.x;
    int base = (blockIdx.x == 0) ? 0 : g_bsum[blockIdx.x - 1];
    if (idx < NN) {
        int v = g_off[idx + 1] + base;
        g_off[idx + 1] = v;
        if (idx + 1 < NN) g_cur[idx + 1] = v;
    }
    if (idx == 0) { g_off[0] = 0; g_cur[0] = 0; }
}

__global__ void k_fill(const int* __restrict__ ei) {
    int e = blockIdx.x * blockDim.x + threadIdx.x;
    if (e < NE) {
        int src = ei[e];
        int dst = ei[NE + e];
        int p = atomicAdd(&g_cur[dst], 1);
        g_esrc[p] = src;
    }
}

// ---------------- mma.sync GEMM: Y = dinv .* (X @ (Wh + Wl)) as fp16 --------
// CTA: 128 rows x 128 cols, 8 warps (4x2), warp tile m32 x n64.
#define GEMM_SMEM (32768 + 65536)
__global__ void __launch_bounds__(256, 2)
k_gemm(const float* __restrict__ Xf, const __half* __restrict__ Xh,
       int wsel, __half* __restrict__ Y, int nrows) {
    extern __shared__ char sm[];
    char* Xs = sm;                               // [128 rows][16 chunks of 16B], swizzled
    uint32_t* Wsm = (uint32_t*)(sm + 32768);     // 16384 u32
    int tid = threadIdx.x, wid = tid >> 5, lane = tid & 31;
    int row0 = blockIdx.x * 128;

    {
        const uint4* src = (const uint4*)g_wpack[wsel];
        uint4* dst = (uint4*)Wsm;
#pragma unroll
        for (int i = 0; i < 16; i++) dst[tid + 256 * i] = src[tid + 256 * i];
    }
    if (Xf) {
        const float4* X4 = (const float4*)Xf;
#pragma unroll
        for (int it = 0; it < 8; it++) {
            int g = tid + 256 * it;
            int r = g >> 4, c = g & 15;
            uint4 o = make_uint4(0, 0, 0, 0);
            if (row0 + r < nrows) {
                float4 a = X4[(size_t)(row0 + r) * 32 + c * 2];
                float4 b = X4[(size_t)(row0 + r) * 32 + c * 2 + 1];
                o.x = h2u(a.x, a.y); o.y = h2u(a.z, a.w);
                o.z = h2u(b.x, b.y); o.w = h2u(b.z, b.w);
            }
            *(uint4*)(Xs + r * 256 + ((c ^ (r & 7)) * 16)) = o;
        }
    } else {
        const uint4* X4 = (const uint4*)Xh;
#pragma unroll
        for (int it = 0; it < 8; it++) {
            int g = tid + 256 * it;
            int r = g >> 4, c = g & 15;
            uint4 o = make_uint4(0, 0, 0, 0);
            if (row0 + r < nrows) o = X4[(size_t)(row0 + r) * 16 + c];
            *(uint4*)(Xs + r * 256 + ((c ^ (r & 7)) * 16)) = o;
        }
    }
    __syncthreads();

    int wr = wid & 3;
    int wc = wid >> 2;
    float acc[2][8][4];
#pragma unroll
    for (int mt = 0; mt < 2; mt++)
#pragma unroll
        for (int nt = 0; nt < 8; nt++)
#pragma unroll
            for (int q = 0; q < 4; q++) acc[mt][nt][q] = 0.f;

    uint32_t smx = smem_u32(Xs);
    const uint2* W2v = (const uint2*)Wsm;

#pragma unroll
    for (int ks = 0; ks < 8; ks++) {
        uint32_t a[2][4];
#pragma unroll
        for (int mt = 0; mt < 2; mt++) {
            int sub = lane >> 3;
            int r = 32 * wr + 16 * mt + (lane & 7) + (sub & 1) * 8;
            int c = ks * 2 + (sub >> 1);
            uint32_t addr = smx + r * 256 + ((c ^ (r & 7)) * 16);
            asm volatile(
                "ldmatrix.sync.aligned.m8n8.x4.shared.b16 {%0,%1,%2,%3}, [%4];"
                : "=r"(a[mt][0]), "=r"(a[mt][1]), "=r"(a[mt][2]), "=r"(a[mt][3])
                : "r"(addr));
        }
#pragma unroll
        for (int nt = 0; nt < 8; nt++) {
            int ntg = 8 * wc + nt;
            uint2 bh = W2v[(ks * 16 + ntg) * 32 + lane];
            uint2 bl = W2v[4096 + (ks * 16 + ntg) * 32 + lane];
            mma16816(acc[0][nt], a[0], bh.x, bh.y);
            mma16816(acc[1][nt], a[1], bh.x, bh.y);
            mma16816(acc[0][nt], a[0], bl.x, bl.y);
            mma16816(acc[1][nt], a[1], bl.x, bl.y);
        }
    }

#pragma unroll
    for (int mt = 0; mt < 2; mt++) {
        int r0 = row0 + 32 * wr + 16 * mt + (lane >> 2);
        int r1 = r0 + 8;
        float s0 = (r0 < nrows) ? g_dinv[r0] : 0.f;
        float s1 = (r1 < nrows) ? g_dinv[r1] : 0.f;
#pragma unroll
        for (int nt = 0; nt < 8; nt++) {
            int col = 64 * wc + 8 * nt + (lane & 3) * 2;
            if (r0 < nrows)
                *(uint32_t*)&Y[(size_t)r0 * FH + col] =
                    h2u(acc[mt][nt][0] * s0, acc[mt][nt][1] * s0);
            if (r1 < nrows)
                *(uint32_t*)&Y[(size_t)r1 * FH + col] =
                    h2u(acc[mt][nt][2] * s1, acc[mt][nt][3] * s1);
        }
    }
}

// ---------------- aggregation: warp/node, 2 edges per iter via LDG.128 ------
// H is dinv-prescaled. out = relu(dinv_d*(sum_src H[src] + H[d]) + b)
// do_pool: 8-warp smem reduction -> 1 (or 8) atomic set(s) per block.
// grid MUST be exactly NN/8 blocks (NN divisible by 8).
__global__ void __launch_bounds__(256)
k_agg(const __half* __restrict__ H, const float* __restrict__ bias,
      const int* __restrict__ batch, __half* __restrict__ OutH, int do_pool) {
    __shared__ float sp[8][128];
    __shared__ int sb[8];
    int warp = threadIdx.x >> 5;
    int lane = threadIdx.x & 31;
    int node = blockIdx.x * 8 + warp;
    int half = lane >> 4;
    int q    = lane & 15;
    int s = g_off[node];
    int e = g_off[node + 1];
    const uint4* H4 = (const uint4*)H;    // row = 16 uint4 (256B)
    float a0 = 0.f, a1 = 0.f, a2 = 0.f, a3 = 0.f,
          a4 = 0.f, a5 = 0.f, a6 = 0.f, a7 = 0.f;
#pragma unroll 2
    for (int j = s + half; j < e; j += 2) {
        int src = __ldg(&g_esrc[j]);
        uint4 v = __ldg(&H4[(size_t)src * 16 + q]);
        float2 p;
        p = __half22float2(*(__half2*)&v.x); a0 += p.x; a1 += p.y;
        p = __half22float2(*(__half2*)&v.y); a2 += p.x; a3 += p.y;
        p = __half22float2(*(__half2*)&v.z); a4 += p.x; a5 += p.y;
        p = __half22float2(*(__half2*)&v.w); a6 += p.x; a7 += p.y;
    }
    a0 += __shfl_xor_sync(0xffffffffu, a0, 16);
    a1 += __shfl_xor_sync(0xffffffffu, a1, 16);
    a2 += __shfl_xor_sync(0xffffffffu, a2, 16);
    a3 += __shfl_xor_sync(0xffffffffu, a3, 16);
    a4 += __shfl_xor_sync(0xffffffffu, a4, 16);
    a5 += __shfl_xor_sync(0xffffffffu, a5, 16);
    a6 += __shfl_xor_sync(0xffffffffu, a6, 16);
    a7 += __shfl_xor_sync(0xffffffffu, a7, 16);
    {   // self term (row already dinv*h)
        uint4 v = __ldg(&H4[(size_t)node * 16 + q]);
        float2 p;
        p = __half22float2(*(__half2*)&v.x); a0 += p.x; a1 += p.y;
        p = __half22float2(*(__half2*)&v.y); a2 += p.x; a3 += p.y;
        p = __half22float2(*(__half2*)&v.z); a4 += p.x; a5 += p.y;
        p = __half22float2(*(__half2*)&v.w); a6 += p.x; a7 += p.y;
    }
    float di = g_dinv[node];
    const float4* B4 = (const float4*)bias;
    float4 bv0 = __ldg(&B4[2 * q]);
    float4 bv1 = __ldg(&B4[2 * q + 1]);
    float r0 = fmaxf(di * a0 + bv0.x, 0.f);
    float r1 = fmaxf(di * a1 + bv0.y, 0.f);
    float r2 = fmaxf(di * a2 + bv0.z, 0.f);
    float r3 = fmaxf(di * a3 + bv0.w, 0.f);
    float r4 = fmaxf(di * a4 + bv1.x, 0.f);
    float r5 = fmaxf(di * a5 + bv1.y, 0.f);
    float r6 = fmaxf(di * a6 + bv1.z, 0.f);
    float r7 = fmaxf(di * a7 + bv1.w, 0.f);
    if (OutH && half == 0) {
        uint4 o;
        o.x = h2u(r0, r1); o.y = h2u(r2, r3);
        o.z = h2u(r4, r5); o.w = h2u(r6, r7);
        ((uint4*)OutH)[(size_t)node * 16 + q] = o;
    }
    if (do_pool) {
        if (half == 0) {
            *(float4*)&sp[warp][8 * q]     = make_float4(r0, r1, r2, r3);
            *(float4*)&sp[warp][8 * q + 4] = make_float4(r4, r5, r6, r7);
        }
        if (lane == 0) sb[warp] = __ldg(&batch[node]);
        __syncthreads();
        int t = threadIdx.x;
        int bg = sb[0];
        bool uni = true;
#pragma unroll
        for (int w = 1; w < 8; w++) uni &= (sb[w] == bg);
        if (t < 128) {
            if (uni) {
                float sum = 0.f;
#pragma unroll
                for (int w = 0; w < 8; w++) sum += sp[w][t];
                atomicAdd(&g_pool[bg * FH + t], sum);
            } else {
#pragma unroll
                for (int w = 0; w < 8; w++)
                    atomicAdd(&g_pool[sb[w] * FH + t], sp[w][t]);
            }
        } else if (uni) {
            if (t == 128) atomicAdd(&g_cnt[bg], 8);
        } else {
            if (t >= 128 && t < 136) atomicAdd(&g_cnt[sb[t - 128]], 1);
        }
    }
}

// ---------------- final MLP head: one block per graph -----------------------
__global__ void k_mlp(const float* __restrict__ Wl1, const float* __restrict__ bl1,
                      const float* __restrict__ Wl2, const float* __restrict__ bl2,
                      float* __restrict__ out) {
    __shared__ float gv[FH];
    __shared__ float tv[FH];
    int b = blockIdx.x, tid = threadIdx.x;
    float c = fmaxf((float)g_cnt[b], 1.0f);
    gv[tid] = g_pool[b * FH + tid] / c;
    __syncthreads();
    float s = bl1[tid];
#pragma unroll 8
    for (int k = 0; k < FH; k++) s += gv[k] * Wl1[k * FH + tid];
    tv[tid] = fmaxf(s, 0.f);
    __syncthreads();
    if (tid < NA) {
        float o = bl2[tid];
#pragma unroll 8
        for (int k = 0; k < FH; k++) o += tv[k] * Wl2[k * NA + tid];
        out[b * NA + tid] = o;
    }
}

// ---------------- launch ----------------------------------------------------
extern "C" void kernel_launch(void* const* d_in, const int* in_sizes, int n_in,
                              void* d_out, int out_size) {
    const float* x   = (const float*)d_in[0];
    const int*   ei  = (const int*)d_in[1];
    const int*   bat = (const int*)d_in[2];
    const float* W1  = (const float*)d_in[3];
    const float* b1  = (const float*)d_in[4];
    const float* W2  = (const float*)d_in[5];
    const float* b2  = (const float*)d_in[6];
    const float* Wl1 = (const float*)d_in[7];
    const float* bl1 = (const float*)d_in[8];
    const float* Wl2 = (const float*)d_in[9];
    const float* bl2 = (const float*)d_in[10];
    float* out = (float*)d_out;

    __half *phh = nullptr, *pth = nullptr;
    cudaGetSymbolAddress((void**)&phh, g_hh);
    cudaGetSymbolAddress((void**)&pth, g_th);

    cudaFuncSetAttribute(k_gemm, cudaFuncAttributeMaxDynamicSharedMemorySize,
                         GEMM_SMEM);

    const int GB = (NN + 127) / 128;   // 782
    const int AB = NN / 8;             // 12500 (NN divisible by 8)

    k_prepw<<<128 + (NN + 255) / 256, 256>>>(W1, W2);            // 1 (wpack+zero)
    k_deg<<<(NE + 255) / 256, 256>>>(ei);                        // 2
    k_scan1<<<SCAN_NB, SCAN_BS>>>();                             // 3 (+dinv)
    k_gemm<<<GB, 256, GEMM_SMEM>>>(x, nullptr, 0, phh, NN);      // 4 [profiled]
    k_scan2<<<1, 256>>>();                                       // 5
    k_scan3<<<SCAN_NB, SCAN_BS>>>();                             // 6 (+cur)
    k_fill<<<(NE + 255) / 256, 256>>>(ei);                       // 7
    k_agg<<<AB, 256>>>(phh, b1, bat, pth, 0);                    // 8
    k_gemm<<<GB, 256, GEMM_SMEM>>>(nullptr, pth, 1, phh, NN);    // 9
    k_agg<<<AB, 256>>>(phh, b2, bat, nullptr, 1);                // 10
    k_mlp<<<NG, FH>>>(Wl1, bl1, Wl2, bl2, out);                  // 11
}

// round 6
// speedup vs baseline: 1.6286x; 1.0114x over previous
#include <cuda_runtime.h>
#include <cuda_fp16.h>
#include <cstdint>

#define NN 100000
#define NE 1600000
#define FH 128
#define NG 256
#define NA 32

#define SCAN_BS 512
#define SCAN_NB ((NN + SCAN_BS - 1) / SCAN_BS)   // 196
#define FILLB 296                                 // fill blocks in fused kernel

// ---------------- scratch (device globals; no runtime allocation) ----------
__device__ __half    g_hh[(size_t)NN * FH];   // dinv-prescaled GEMM output (25.6MB)
__device__ __half    g_th[(size_t)NN * FH];   // layer-1 output t (25.6MB)
__device__ int       g_deg[NN];
__device__ float     g_dinv[NN];
__device__ int       g_off[NN + 1];
__device__ int       g_cur[NN];
__device__ int       g_esrc[NE];
__device__ int       g_bsum[SCAN_NB];
__device__ float     g_pool[NG * FH];
__device__ int       g_cnt[NG];
// W packed per-lane mma B fragments, hi/lo interleaved:
// [wsel][(ks*16+nt)*32+lane] = uint4{hi_r0, hi_r1, lo_r0, lo_r1}
__device__ uint4     g_wpack[2][4096];

// ---------------- helpers ---------------------------------------------------
__device__ __forceinline__ uint32_t smem_u32(const void* p) {
    uint32_t a;
    asm("{ .reg .u64 t; cvta.to.shared.u64 t, %1; cvt.u32.u64 %0, t; }"
        : "=r"(a) : "l"(p));
    return a;
}
__device__ __forceinline__ uint32_t h2u(float a, float b) {
    __half2 h = __floats2half2_rn(a, b);
    return *(uint32_t*)&h;
}
__device__ __forceinline__ void mma16816(float* c, const uint32_t* a,
                                         uint32_t b0, uint32_t b1) {
    asm volatile(
        "mma.sync.aligned.m16n8k16.row.col.f32.f16.f16.f32 "
        "{%0,%1,%2,%3}, {%4,%5,%6,%7}, {%8,%9}, {%0,%1,%2,%3};"
        : "+f"(c[0]), "+f"(c[1]), "+f"(c[2]), "+f"(c[3])
        : "r"(a[0]), "r"(a[1]), "r"(a[2]), "r"(a[3]), "r"(b0), "r"(b1));
}

// -------- weight prep (blocks <32) fused with scratch zeroing (rest) --------
__global__ void k_prepw(const float* __restrict__ W1, const float* __restrict__ W2) {
    if (blockIdx.x >= 32) {
        int i = (blockIdx.x - 32) * 256 + threadIdx.x;
        if (i < NN) g_deg[i] = 0;
        if (i < NG * FH) g_pool[i] = 0.f;
        if (i < NG) g_cnt[i] = 0;
        return;
    }
    int gid = blockIdx.x * 256 + threadIdx.x;   // < 8192
    int wsel = gid >> 12;
    int rem  = gid & 4095;
    int ks   = rem >> 9;
    int nt   = (rem >> 5) & 15;
    int lane = rem & 31;
    const float* W = wsel ? W2 : W1;
    int n = nt * 8 + (lane >> 2);
    uint32_t h[2], l[2];
#pragma unroll
    for (int reg = 0; reg < 2; reg++) {
        int k = ks * 16 + (lane & 3) * 2 + reg * 8;
        float v0 = W[k * FH + n];
        float v1 = W[(k + 1) * FH + n];
        __half h0 = __float2half_rn(v0);
        __half h1 = __float2half_rn(v1);
        __half l0 = __float2half_rn(v0 - __half2float(h0));
        __half l1 = __float2half_rn(v1 - __half2float(h1));
        __half2 hp = __halves2half2(h0, h1);
        __half2 lp = __halves2half2(l0, l1);
        h[reg] = *(uint32_t*)&hp;
        l[reg] = *(uint32_t*)&lp;
    }
    g_wpack[wsel][(ks * 16 + nt) * 32 + lane] = make_uint4(h[0], h[1], l[0], l[1]);
}

// ---------------- CSR build --------------------------------------------------
__global__ void k_deg(const int* __restrict__ ei) {
    int e4 = blockIdx.x * blockDim.x + threadIdx.x;
    if (e4 < NE / 4) {
        int4 d = __ldg(&((const int4*)(ei + NE))[e4]);
        atomicAdd(&g_deg[d.x], 1);
        atomicAdd(&g_deg[d.y], 1);
        atomicAdd(&g_deg[d.z], 1);
        atomicAdd(&g_deg[d.w], 1);
    }
}

__global__ void k_scan1() {
    __shared__ int s[SCAN_BS];
    int idx = blockIdx.x * SCAN_BS + threadIdx.x;
    int v = (idx < NN) ? g_deg[idx] : 0;
    if (idx < NN) g_dinv[idx] = rsqrtf((float)v + 1.0f);
    s[threadIdx.x] = v;
    __syncthreads();
    for (int d = 1; d < SCAN_BS; d <<= 1) {
        int t = (threadIdx.x >= d) ? s[threadIdx.x - d] : 0;
        __syncthreads();
        s[threadIdx.x] += t;
        __syncthreads();
    }
    if (idx < NN) g_off[idx + 1] = s[threadIdx.x];
    if (threadIdx.x == SCAN_BS - 1) g_bsum[blockIdx.x] = s[SCAN_BS - 1];
}

// scan of block sums (done redundantly per block) + offset/cursor finalize
__global__ void k_scan23() {
    __shared__ int sb[256];
    int tid = threadIdx.x;
    if (tid < 256) sb[tid] = (tid < SCAN_NB) ? g_bsum[tid] : 0;
    __syncthreads();
    for (int d = 1; d < 256; d <<= 1) {
        int t = 0;
        if (tid < 256 && tid >= d) t = sb[tid - d];
        __syncthreads();
        if (tid < 256) sb[tid] += t;
        __syncthreads();
    }
    int base = (blockIdx.x == 0) ? 0 : sb[blockIdx.x - 1];
    int idx = blockIdx.x * SCAN_BS + tid;
    if (idx < NN) {
        int v = g_off[idx + 1] + base;
        g_off[idx + 1] = v;
        if (idx + 1 < NN) g_cur[idx + 1] = v;
    }
    if (idx == 0) { g_off[0] = 0; g_cur[0] = 0; }
}

// ---------------- fused CSR-fill (+) mma.sync GEMM --------------------------
// Blocks [0, fb): grid-stride CSR fill (atomic cursor scatter).
// Blocks [fb, ...): 256 rows x 128 cols per CTA (2 sub-tiles share one W copy).
// Y = dinv .* (X @ (Wh + Wl)), stored fp16.
#define GEMM_SMEM (32768 + 65536)
__global__ void __launch_bounds__(256, 2)
k_gemm(const float* __restrict__ Xf, const __half* __restrict__ Xh,
       int wsel, __half* __restrict__ Y, int nrows,
       const int* __restrict__ ei, int fb) {
    int tid = threadIdx.x;
    if ((int)blockIdx.x < fb) {
        int stride = fb * 256;
        for (int e = blockIdx.x * 256 + tid; e < NE; e += stride) {
            int src = __ldg(&ei[e]);
            int dst = __ldg(&ei[NE + e]);
            int p = atomicAdd(&g_cur[dst], 1);
            g_esrc[p] = src;
        }
        return;
    }
    extern __shared__ char sm[];
    char* Xs = sm;                            // [128 rows][16 chunks of 16B], swizzled
    uint4* Wsm = (uint4*)(sm + 32768);        // 4096 uint4 (64KB)
    int wid = tid >> 5, lane = tid & 31;
    int tile0 = (blockIdx.x - fb) * 256;

    {   // copy packed W once (64KB)
        const uint4* src = g_wpack[wsel];
#pragma unroll
        for (int i = 0; i < 16; i++) Wsm[tid + 256 * i] = src[tid + 256 * i];
    }

    int wr = wid & 3;
    int wc = wid >> 2;
    uint32_t smx = smem_u32(Xs);

#pragma unroll
    for (int sub = 0; sub < 2; sub++) {
        int row0 = tile0 + sub * 128;
        if (row0 >= nrows) break;             // uniform across CTA
        if (sub) __syncthreads();             // protect Xs reuse
        if (Xf) {
            const float4* X4 = (const float4*)Xf;
#pragma unroll
            for (int it = 0; it < 8; it++) {
                int g = tid + 256 * it;
                int r = g >> 4, c = g & 15;
                uint4 o = make_uint4(0, 0, 0, 0);
                if (row0 + r < nrows) {
                    float4 a = X4[(size_t)(row0 + r) * 32 + c * 2];
                    float4 b = X4[(size_t)(row0 + r) * 32 + c * 2 + 1];
                    o.x = h2u(a.x, a.y); o.y = h2u(a.z, a.w);
                    o.z = h2u(b.x, b.y); o.w = h2u(b.z, b.w);
                }
                *(uint4*)(Xs + r * 256 + ((c ^ (r & 7)) * 16)) = o;
            }
        } else {
            const uint4* X4 = (const uint4*)Xh;
#pragma unroll
            for (int it = 0; it < 8; it++) {
                int g = tid + 256 * it;
                int r = g >> 4, c = g & 15;
                uint4 o = make_uint4(0, 0, 0, 0);
                if (row0 + r < nrows) o = X4[(size_t)(row0 + r) * 16 + c];
                *(uint4*)(Xs + r * 256 + ((c ^ (r & 7)) * 16)) = o;
            }
        }
        __syncthreads();

        float acc[2][8][4];
#pragma unroll
        for (int mt = 0; mt < 2; mt++)
#pragma unroll
            for (int nt = 0; nt < 8; nt++)
#pragma unroll
                for (int q = 0; q < 4; q++) acc[mt][nt][q] = 0.f;

#pragma unroll
        for (int ks = 0; ks < 8; ks++) {
            uint32_t a[2][4];
#pragma unroll
            for (int mt = 0; mt < 2; mt++) {
                int sb2 = lane >> 3;
                int r = 32 * wr + 16 * mt + (lane & 7) + (sb2 & 1) * 8;
                int c = ks * 2 + (sb2 >> 1);
                uint32_t addr = smx + r * 256 + ((c ^ (r & 7)) * 16);
                asm volatile(
                    "ldmatrix.sync.aligned.m8n8.x4.shared.b16 {%0,%1,%2,%3}, [%4];"
                    : "=r"(a[mt][0]), "=r"(a[mt][1]), "=r"(a[mt][2]), "=r"(a[mt][3])
                    : "r"(addr));
            }
#pragma unroll
            for (int nt = 0; nt < 8; nt++) {
                int ntg = 8 * wc + nt;
                uint4 b = Wsm[(ks * 16 + ntg) * 32 + lane];
                mma16816(acc[0][nt], a[0], b.x, b.y);
                mma16816(acc[1][nt], a[1], b.x, b.y);
                mma16816(acc[0][nt], a[0], b.z, b.w);
                mma16816(acc[1][nt], a[1], b.z, b.w);
            }
        }

#pragma unroll
        for (int mt = 0; mt < 2; mt++) {
            int r0 = row0 + 32 * wr + 16 * mt + (lane >> 2);
            int r1 = r0 + 8;
            float s0 = (r0 < nrows) ? g_dinv[r0] : 0.f;
            float s1 = (r1 < nrows) ? g_dinv[r1] : 0.f;
#pragma unroll
            for (int nt = 0; nt < 8; nt++) {
                int col = 64 * wc + 8 * nt + (lane & 3) * 2;
                if (r0 < nrows)
                    *(uint32_t*)&Y[(size_t)r0 * FH + col] =
                        h2u(acc[mt][nt][0] * s0, acc[mt][nt][1] * s0);
                if (r1 < nrows)
                    *(uint32_t*)&Y[(size_t)r1 * FH + col] =
                        h2u(acc[mt][nt][2] * s1, acc[mt][nt][3] * s1);
            }
        }
    }
}

// ---------------- aggregation: warp/node, 2 edges per iter via LDG.128 ------
__global__ void __launch_bounds__(256)
k_agg(const __half* __restrict__ H, const float* __restrict__ bias,
      const int* __restrict__ batch, __half* __restrict__ OutH, int do_pool) {
    __shared__ float sp[8][128];
    __shared__ int sb[8];
    int warp = threadIdx.x >> 5;
    int lane = threadIdx.x & 31;
    int node = blockIdx.x * 8 + warp;
    int half = lane >> 4;
    int q    = lane & 15;
    int s = g_off[node];
    int e = g_off[node + 1];
    const uint4* H4 = (const uint4*)H;
    float a0 = 0.f, a1 = 0.f, a2 = 0.f, a3 = 0.f,
          a4 = 0.f, a5 = 0.f, a6 = 0.f, a7 = 0.f;
#pragma unroll 2
    for (int j = s + half; j < e; j += 2) {
        int src = __ldg(&g_esrc[j]);
        uint4 v = __ldg(&H4[(size_t)src * 16 + q]);
        float2 p;
        p = __half22float2(*(__half2*)&v.x); a0 += p.x; a1 += p.y;
        p = __half22float2(*(__half2*)&v.y); a2 += p.x; a3 += p.y;
        p = __half22float2(*(__half2*)&v.z); a4 += p.x; a5 += p.y;
        p = __half22float2(*(__half2*)&v.w); a6 += p.x; a7 += p.y;
    }
    a0 += __shfl_xor_sync(0xffffffffu, a0, 16);
    a1 += __shfl_xor_sync(0xffffffffu, a1, 16);
    a2 += __shfl_xor_sync(0xffffffffu, a2, 16);
    a3 += __shfl_xor_sync(0xffffffffu, a3, 16);
    a4 += __shfl_xor_sync(0xffffffffu, a4, 16);
    a5 += __shfl_xor_sync(0xffffffffu, a5, 16);
    a6 += __shfl_xor_sync(0xffffffffu, a6, 16);
    a7 += __shfl_xor_sync(0xffffffffu, a7, 16);
    {   // self term (row already dinv*h)
        uint4 v = __ldg(&H4[(size_t)node * 16 + q]);
        float2 p;
        p = __half22float2(*(__half2*)&v.x); a0 += p.x; a1 += p.y;
        p = __half22float2(*(__half2*)&v.y); a2 += p.x; a3 += p.y;
        p = __half22float2(*(__half2*)&v.z); a4 += p.x; a5 += p.y;
        p = __half22float2(*(__half2*)&v.w); a6 += p.x; a7 += p.y;
    }
    float di = g_dinv[node];
    const float4* B4 = (const float4*)bias;
    float4 bv0 = __ldg(&B4[2 * q]);
    float4 bv1 = __ldg(&B4[2 * q + 1]);
    float r0 = fmaxf(di * a0 + bv0.x, 0.f);
    float r1 = fmaxf(di * a1 + bv0.y, 0.f);
    float r2 = fmaxf(di * a2 + bv0.z, 0.f);
    float r3 = fmaxf(di * a3 + bv0.w, 0.f);
    float r4 = fmaxf(di * a4 + bv1.x, 0.f);
    float r5 = fmaxf(di * a5 + bv1.y, 0.f);
    float r6 = fmaxf(di * a6 + bv1.z, 0.f);
    float r7 = fmaxf(di * a7 + bv1.w, 0.f);
    if (OutH && half == 0) {
        uint4 o;
        o.x = h2u(r0, r1); o.y = h2u(r2, r3);
        o.z = h2u(r4, r5); o.w = h2u(r6, r7);
        ((uint4*)OutH)[(size_t)node * 16 + q] = o;
    }
    if (do_pool) {
        if (half == 0) {
            *(float4*)&sp[warp][8 * q]     = make_float4(r0, r1, r2, r3);
            *(float4*)&sp[warp][8 * q + 4] = make_float4(r4, r5, r6, r7);
        }
        if (lane == 0) sb[warp] = __ldg(&batch[node]);
        __syncthreads();
        int t = threadIdx.x;
        int bg = sb[0];
        bool uni = true;
#pragma unroll
        for (int w = 1; w < 8; w++) uni &= (sb[w] == bg);
        if (t < 128) {
            if (uni) {
                float sum = 0.f;
#pragma unroll
                for (int w = 0; w < 8; w++) sum += sp[w][t];
                atomicAdd(&g_pool[bg * FH + t], sum);
            } else {
#pragma unroll
                for (int w = 0; w < 8; w++)
                    atomicAdd(&g_pool[sb[w] * FH + t], sp[w][t]);
            }
        } else if (uni) {
            if (t == 128) atomicAdd(&g_cnt[bg], 8);
        } else {
            if (t >= 128 && t < 136) atomicAdd(&g_cnt[sb[t - 128]], 1);
        }
    }
}

// ---------------- final MLP head: one block per graph -----------------------
__global__ void k_mlp(const float* __restrict__ Wl1, const float* __restrict__ bl1,
                      const float* __restrict__ Wl2, const float* __restrict__ bl2,
                      float* __restrict__ out) {
    __shared__ float gv[FH];
    __shared__ float tv[FH];
    int b = blockIdx.x, tid = threadIdx.x;
    float c = fmaxf((float)g_cnt[b], 1.0f);
    gv[tid] = g_pool[b * FH + tid] / c;
    __syncthreads();
    float s = bl1[tid];
#pragma unroll 8
    for (int k = 0; k < FH; k++) s += gv[k] * Wl1[k * FH + tid];
    tv[tid] = fmaxf(s, 0.f);
    __syncthreads();
    if (tid < NA) {
        float o = bl2[tid];
#pragma unroll 8
        for (int k = 0; k < FH; k++) o += tv[k] * Wl2[k * NA + tid];
        out[b * NA + tid] = o;
    }
}

// ---------------- launch ----------------------------------------------------
extern "C" void kernel_launch(void* const* d_in, const int* in_sizes, int n_in,
                              void* d_out, int out_size) {
    const float* x   = (const float*)d_in[0];
    const int*   ei  = (const int*)d_in[1];
    const int*   bat = (const int*)d_in[2];
    const float* W1  = (const float*)d_in[3];
    const float* b1  = (const float*)d_in[4];
    const float* W2  = (const float*)d_in[5];
    const float* b2  = (const float*)d_in[6];
    const float* Wl1 = (const float*)d_in[7];
    const float* bl1 = (const float*)d_in[8];
    const float* Wl2 = (const float*)d_in[9];
    const float* bl2 = (const float*)d_in[10];
    float* out = (float*)d_out;

    __half *phh = nullptr, *pth = nullptr;
    cudaGetSymbolAddress((void**)&phh, g_hh);
    cudaGetSymbolAddress((void**)&pth, g_th);

    cudaFuncSetAttribute(k_gemm, cudaFuncAttributeMaxDynamicSharedMemorySize,
                         GEMM_SMEM);

    const int GB = (NN + 255) / 256;   // 391
    const int AB = NN / 8;             // 12500

    k_prepw<<<32 + (NN + 255) / 256, 256>>>(W1, W2);             // 1 (wpack+zero)
    k_deg<<<(NE / 4 + 255) / 256, 256>>>(ei);                    // 2
    k_scan1<<<SCAN_NB, SCAN_BS>>>();                             // 3 (+dinv)
    k_scan23<<<SCAN_NB, SCAN_BS>>>();                            // 4 (+cur)
    // 5: fused CSR-fill + layer-1 GEMM (prescaled epilogue, dinv ready)
    k_gemm<<<FILLB + GB, 256, GEMM_SMEM>>>(x, nullptr, 0, phh, NN, ei, FILLB);
    k_agg<<<AB, 256>>>(phh, b1, bat, pth, 0);                    // 6
    k_gemm<<<GB, 256, GEMM_SMEM>>>(nullptr, pth, 1, phh, NN, ei, 0); // 7
    k_agg<<<AB, 256>>>(phh, b2, bat, nullptr, 1);                // 8
    k_mlp<<<NG, FH>>>(Wl1, bl1, Wl2, bl2, out);                  // 9
}